// round 14
// baseline (speedup 1.0000x reference)
#include <cuda_runtime.h>
#include <cuda_bf16.h>
#include <math.h>

// ---------------- device state (no allocations allowed) ----------------
__device__ float g_h2[2 * 1024];        // prefill hidden (2 tokens)
__device__ float g_hdec[1024];          // decode hidden
__device__ float g_q[2 * 1024];         // roped q per token
__device__ float g_kc[2][16][1024];     // k cache [layer][pos][NH*HD]
__device__ float g_vc[2][16][1024];     // v cache
__device__ float g_ff[2 * 4096];        // mlp intermediate
__device__ float g_logits[2048];
__device__ float g_embed_sum[1024];
__device__ int   g_codes[16];

// ---------------- helpers ----------------
__device__ __forceinline__ float block_sum(float v, float* red) {
    int lane = threadIdx.x & 31, w = threadIdx.x >> 5;
    #pragma unroll
    for (int o = 16; o; o >>= 1) v += __shfl_xor_sync(0xffffffffu, v, o);
    if (lane == 0) red[w] = v;
    __syncthreads();
    float r = (threadIdx.x < (blockDim.x >> 5)) ? red[threadIdx.x] : 0.f;
    if (w == 0) {
        #pragma unroll
        for (int o = 16; o; o >>= 1) r += __shfl_xor_sync(0xffffffffu, r, o);
        if (lane == 0) red[0] = r;
    }
    __syncthreads();
    float out = red[0];
    __syncthreads();
    return out;
}

// redundant per-block RMS norm into shared memory
__device__ __forceinline__ void load_rms(const float* h, const float* w,
                                         float* xs, int T, float* red) {
    for (int t = 0; t < T; t++) {
        float ss = 0.f;
        for (int i = threadIdx.x; i < 1024; i += 256) {
            float v = h[t * 1024 + i];
            ss += v * v;
        }
        float tot = block_sum(ss, red);
        float rn = rsqrtf(tot * (1.f / 1024.f) + 1e-6f);
        for (int i = threadIdx.x; i < 1024; i += 256)
            xs[t * 1024 + i] = h[t * 1024 + i] * rn * w[i];
    }
    __syncthreads();
}

__device__ __forceinline__ float gelu_tanh(float v) {
    float u = 0.7978845608028654f * (v + 0.044715f * v * v * v);
    return 0.5f * v * (1.f + tanhf(u));
}

// ---------------- kernels ----------------

__global__ void k_init(const float* __restrict__ talker,
                       const float* __restrict__ code0) {
    for (int i = threadIdx.x; i < 1024; i += 256) {
        g_h2[i]        = talker[i];
        g_h2[1024 + i] = code0[i];
        g_embed_sum[i] = code0[i];
    }
}

// QKV GEMV + RoPE + KV cache write. grid=96, block=256.
// pair index p in [0,1536): m = p>>9 (0=q,1=k,2=v), head=(p>>5)&15, d=p&31.
__global__ void k_qkv(const float* __restrict__ wq, const float* __restrict__ wk,
                      const float* __restrict__ wv, const float* __restrict__ ln1,
                      int l, int T, int p0, int hsel) {
    __shared__ float xs[2 * 1024];
    __shared__ float red[32];
    __shared__ float p1s[16][16][2];
    __shared__ float p2s[16][16][2];
    const float* h = hsel ? g_hdec : g_h2;
    load_rms(h, ln1 + l * 1024, xs, T, red);

    int pp = threadIdx.x & 15, ks = threadIdx.x >> 4;
    int pidx = blockIdx.x * 16 + pp;
    int m = pidx >> 9, head = (pidx >> 5) & 15, d = pidx & 31;
    const float* base = (m == 0) ? wq : ((m == 1) ? wk : wv);
    const float* W = base + (size_t)l * 1024 * 1024 + head * 64 + d;

    float a1[2] = {0.f, 0.f}, a2[2] = {0.f, 0.f};
    int i0 = ks * 64;
    #pragma unroll 4
    for (int i = i0; i < i0 + 64; i++) {
        float wa = W[(size_t)i * 1024];
        float wb = W[(size_t)i * 1024 + 32];
        a1[0] += xs[i] * wa; a2[0] += xs[i] * wb;
        if (T == 2) { a1[1] += xs[1024 + i] * wa; a2[1] += xs[1024 + i] * wb; }
    }
    p1s[ks][pp][0] = a1[0]; p2s[ks][pp][0] = a2[0];
    p1s[ks][pp][1] = a1[1]; p2s[ks][pp][1] = a2[1];
    __syncthreads();

    if (threadIdx.x < 16) {
        int ppi = threadIdx.x;
        int pidx2 = blockIdx.x * 16 + ppi;
        int mm = pidx2 >> 9, hh = (pidx2 >> 5) & 15, dd = pidx2 & 31;
        for (int t = 0; t < T; t++) {
            float s1 = 0.f, s2 = 0.f;
            #pragma unroll
            for (int k2 = 0; k2 < 16; k2++) { s1 += p1s[k2][ppi][t]; s2 += p2s[k2][ppi][t]; }
            float o1 = s1, o2 = s2;
            if (mm < 2) {
                float inv = powf(10000.f, -(float)dd * (1.f / 32.f));
                float ang = (float)(p0 + t) * inv;
                float c = cosf(ang), s = sinf(ang);
                o1 = s1 * c - s2 * s;
                o2 = s2 * c + s1 * s;
            }
            int off = hh * 64 + dd;
            if (mm == 0)      { g_q[t * 1024 + off] = o1; g_q[t * 1024 + off + 32] = o2; }
            else if (mm == 1) { g_kc[l][p0 + t][off] = o1; g_kc[l][p0 + t][off + 32] = o2; }
            else              { g_vc[l][p0 + t][off] = o1; g_vc[l][p0 + t][off + 32] = o2; }
        }
    }
}

// fused attention (redundant per block) + o-proj GEMV + residual. grid=64, block=256.
__global__ void k_attn_o(const float* __restrict__ wo, int l, int T, int p0, int hsel) {
    __shared__ float ao[2][1024];
    __shared__ float pr[16][16][2];
    float* h = hsel ? g_hdec : g_h2;
    int warp = threadIdx.x >> 5, lane = threadIdx.x & 31;

    for (int idx = warp; idx < T * 16; idx += 8) {
        int t = idx >> 4, hh = idx & 15;
        int S = p0 + t + 1;
        const float* qp = g_q + t * 1024 + hh * 64;
        float q0 = qp[lane], q1 = qp[lane + 32];
        float sc[16];
        for (int s = 0; s < S; s++) {
            const float* kp = &g_kc[l][s][hh * 64];
            float p = q0 * kp[lane] + q1 * kp[lane + 32];
            #pragma unroll
            for (int o = 16; o; o >>= 1) p += __shfl_xor_sync(0xffffffffu, p, o);
            sc[s] = p * 0.125f;
        }
        float mx = sc[0];
        for (int s = 1; s < S; s++) mx = fmaxf(mx, sc[s]);
        float den = 0.f;
        for (int s = 0; s < S; s++) { sc[s] = expf(sc[s] - mx); den += sc[s]; }
        float dn = 1.f / den;
        float o0 = 0.f, o1 = 0.f;
        for (int s = 0; s < S; s++) {
            const float* vp = &g_vc[l][s][hh * 64];
            float pw = sc[s] * dn;
            o0 += pw * vp[lane];
            o1 += pw * vp[lane + 32];
        }
        ao[t][hh * 64 + lane]      = o0;
        ao[t][hh * 64 + lane + 32] = o1;
    }
    __syncthreads();

    int c = threadIdx.x & 15, ks = threadIdx.x >> 4;
    int col = blockIdx.x * 16 + c;
    const float* W = wo + (size_t)l * 1024 * 1024 + col;
    float acc[2] = {0.f, 0.f};
    int i0 = ks * 64;
    #pragma unroll 4
    for (int i = i0; i < i0 + 64; i++) {
        float wv = W[(size_t)i * 1024];
        acc[0] += ao[0][i] * wv;
        if (T == 2) acc[1] += ao[1][i] * wv;
    }
    pr[ks][c][0] = acc[0]; pr[ks][c][1] = acc[1];
    __syncthreads();
    if (threadIdx.x < 16) {
        int cc = threadIdx.x;
        int col2 = blockIdx.x * 16 + cc;
        for (int t = 0; t < T; t++) {
            float s = 0.f;
            #pragma unroll
            for (int k2 = 0; k2 < 16; k2++) s += pr[k2][cc][t];
            h[t * 1024 + col2] += s;
        }
    }
}

// RMS + W1 GEMV + gelu -> g_ff. grid=128, block=256.
__global__ void k_mlp1(const float* __restrict__ w1, const float* __restrict__ ln2,
                       int l, int T, int hsel) {
    __shared__ float xs[2 * 1024];
    __shared__ float red[32];
    __shared__ float pr[8][32][2];
    const float* h = hsel ? g_hdec : g_h2;
    load_rms(h, ln2 + l * 1024, xs, T, red);

    int c = threadIdx.x & 31, ks = threadIdx.x >> 5;  // 8 slices x 128 rows
    int col = blockIdx.x * 32 + c;
    const float* W = w1 + (size_t)l * 1024 * 4096 + col;
    float acc[2] = {0.f, 0.f};
    int i0 = ks * 128;
    #pragma unroll 4
    for (int i = i0; i < i0 + 128; i++) {
        float wv = W[(size_t)i * 4096];
        acc[0] += xs[i] * wv;
        if (T == 2) acc[1] += xs[1024 + i] * wv;
    }
    pr[ks][c][0] = acc[0]; pr[ks][c][1] = acc[1];
    __syncthreads();
    if (threadIdx.x < 32) {
        int cc = threadIdx.x;
        int col2 = blockIdx.x * 32 + cc;
        for (int t = 0; t < T; t++) {
            float s = 0.f;
            #pragma unroll
            for (int k2 = 0; k2 < 8; k2++) s += pr[k2][cc][t];
            g_ff[t * 4096 + col2] = gelu_tanh(s);
        }
    }
}

// W2 GEMV + residual. grid=128, block=256.
__global__ void k_mlp2(const float* __restrict__ w2, int l, int T, int hsel) {
    __shared__ float ffs[2 * 4096];
    __shared__ float pr[32][8][2];
    float* h = hsel ? g_hdec : g_h2;
    for (int i = threadIdx.x; i < T * 4096; i += 256) ffs[i] = g_ff[i];
    __syncthreads();

    int c = threadIdx.x & 7, ks = threadIdx.x >> 3;  // 32 slices x 128 rows
    int col = blockIdx.x * 8 + c;
    const float* W = w2 + (size_t)l * 4096 * 1024 + col;
    float acc[2] = {0.f, 0.f};
    int i0 = ks * 128;
    #pragma unroll 4
    for (int i = i0; i < i0 + 128; i++) {
        float wv = W[(size_t)i * 1024];
        acc[0] += ffs[i] * wv;
        if (T == 2) acc[1] += ffs[4096 + i] * wv;
    }
    pr[ks][c][0] = acc[0]; pr[ks][c][1] = acc[1];
    __syncthreads();
    if (threadIdx.x < 8) {
        int cc = threadIdx.x;
        int col2 = blockIdx.x * 8 + cc;
        for (int t = 0; t < T; t++) {
            float s = 0.f;
            #pragma unroll
            for (int k2 = 0; k2 < 32; k2++) s += pr[k2][cc][t];
            h[t * 1024 + col2] += s;
        }
    }
}

// hidden = rms(h,ln_f); logits = heads[g] @ hidden. grid=128, block=256 (8 warps x 2 rows).
__global__ void k_logits(const float* __restrict__ heads, const float* __restrict__ lnf,
                         int g, int hsel) {
    __shared__ float hid[1024];
    __shared__ float red[32];
    const float* h = hsel ? g_hdec : (g_h2 + 1024);
    float ss = 0.f;
    for (int i = threadIdx.x; i < 1024; i += 256) { float v = h[i]; ss += v * v; }
    float tot = block_sum(ss, red);
    float rn = rsqrtf(tot * (1.f / 1024.f) + 1e-6f);
    for (int i = threadIdx.x; i < 1024; i += 256) hid[i] = h[i] * rn * lnf[i];
    __syncthreads();

    int warp = threadIdx.x >> 5, lane = threadIdx.x & 31;
    const float4* xp = (const float4*)hid;
    for (int r = 0; r < 2; r++) {
        int row = blockIdx.x * 16 + warp * 2 + r;
        const float4* rp = (const float4*)(heads + ((size_t)g * 2048 + row) * 1024);
        float acc = 0.f;
        #pragma unroll 8
        for (int j = lane; j < 256; j += 32) {
            float4 a = rp[j], b = xp[j];
            acc += a.x * b.x + a.y * b.y + a.z * b.z + a.w * b.w;
        }
        #pragma unroll
        for (int o = 16; o; o >>= 1) acc += __shfl_xor_sync(0xffffffffu, acc, o);
        if (lane == 0) g_logits[row] = acc;
    }
}

// top-50 (bitonic full sort) + softmax sampling + embed gather/accumulate. 1 block, 256 thr.
__global__ void k_sample(const float* __restrict__ embeds, const float* __restrict__ temp,
                         const float* __restrict__ uniforms, int g) {
    __shared__ unsigned long long keys[2048];
    __shared__ int s_code;
    int tid = threadIdx.x;
    for (int v = tid; v < 2048; v += 256) {
        unsigned int b = __float_as_uint(g_logits[v]);
        unsigned int ord = (b & 0x80000000u) ? ~b : (b | 0x80000000u);
        keys[v] = ((unsigned long long)ord << 32) | (unsigned int)(2047 - v);
    }
    __syncthreads();
    // descending bitonic sort (primary: value desc, secondary: index asc)
    for (int k = 2; k <= 2048; k <<= 1) {
        for (int j = k >> 1; j > 0; j >>= 1) {
            for (int i = tid; i < 2048; i += 256) {
                int ixj = i ^ j;
                if (ixj > i) {
                    bool dir = ((i & k) == 0);  // true => descending segment
                    unsigned long long a = keys[i], b2 = keys[ixj];
                    if (dir ? (a < b2) : (a > b2)) { keys[i] = b2; keys[ixj] = a; }
                }
            }
            __syncthreads();
        }
    }
    if (tid == 0) {
        float t = fmaxf(temp[0], 1e-5f);
        float topv[50];
        int topi[50];
        for (int i = 0; i < 50; i++) {
            unsigned long long kk = keys[i];
            unsigned int ord = (unsigned int)(kk >> 32);
            unsigned int b = (ord & 0x80000000u) ? (ord & 0x7fffffffu) : ~ord;
            topv[i] = __uint_as_float(b);
            topi[i] = 2047 - (int)(kk & 0xffffffffu);
        }
        float inv_t = 1.f / t;
        float mx = topv[0] * inv_t;
        float e[50];
        float den = 0.f;
        for (int i = 0; i < 50; i++) { e[i] = expf(topv[i] * inv_t - mx); den += e[i]; }
        float u = uniforms[g];
        u = fminf(fmaxf(u, 1e-6f), 1.f - 1e-6f);
        float cdf = 0.f;
        int choice = 0;
        bool found = false;
        for (int i = 0; i < 50; i++) {
            cdf += e[i] / den;
            if (!found && cdf >= u) { choice = i; found = true; }
        }
        s_code = topi[choice];
        g_codes[g] = s_code;
    }
    __syncthreads();
    int code = s_code;
    const float* emb = embeds + ((size_t)g * 2048 + code) * 1024;
    for (int i = tid; i < 1024; i += 256) {
        float e2 = emb[i];
        g_embed_sum[i] += e2;
        g_hdec[i] = e2;  // input for next transformer step
    }
}

__global__ void k_out(float* __restrict__ out, int out_size) {
    for (int i = threadIdx.x; i < out_size && i < 1039; i += 256) {
        if (i < 15) out[i] = (float)g_codes[i];
        else        out[i] = g_embed_sum[i - 15];
    }
}

// ---------------- launch ----------------
extern "C" void kernel_launch(void* const* d_in, const int* in_sizes, int n_in,
                              void* d_out, int out_size) {
    (void)in_sizes; (void)n_in;
    const float* talker   = (const float*)d_in[0];
    const float* code0    = (const float*)d_in[1];
    const float* temp     = (const float*)d_in[2];
    const float* uniforms = (const float*)d_in[3];
    const float* heads    = (const float*)d_in[4];
    const float* embeds   = (const float*)d_in[5];
    const float* ln1      = (const float*)d_in[6];
    const float* ln2      = (const float*)d_in[7];
    const float* lnf      = (const float*)d_in[8];
    const float* wq       = (const float*)d_in[9];
    const float* wk       = (const float*)d_in[10];
    const float* wv       = (const float*)d_in[11];
    const float* wo       = (const float*)d_in[12];
    const float* w1       = (const float*)d_in[13];
    const float* w2       = (const float*)d_in[14];

    k_init<<<1, 256>>>(talker, code0);

    // prefill: T=2, positions 0..1, h buffer = g_h2 (hsel=0)
    for (int l = 0; l < 2; l++) {
        k_qkv  <<<96, 256>>>(wq, wk, wv, ln1, l, 2, 0, 0);
        k_attn_o<<<64, 256>>>(wo, l, 2, 0, 0);
        k_mlp1 <<<128, 256>>>(w1, ln2, l, 2, 0);
        k_mlp2 <<<128, 256>>>(w2, l, 2, 0);
    }

    for (int g = 0; g < 15; g++) {
        k_logits<<<128, 256>>>(heads, lnf, g, (g == 0) ? 0 : 1);
        k_sample<<<1, 256>>>(embeds, temp, uniforms, g);
        if (g < 14) {
            int p0 = g + 2;  // new token position; cache len before step = p0
            for (int l = 0; l < 2; l++) {
                k_qkv  <<<96, 256>>>(wq, wk, wv, ln1, l, 1, p0, 1);
                k_attn_o<<<64, 256>>>(wo, l, 1, p0, 1);
                k_mlp1 <<<128, 256>>>(w1, ln2, l, 1, 1);
                k_mlp2 <<<128, 256>>>(w2, l, 1, 1);
            }
        }
    }

    k_out<<<1, 256>>>((float*)d_out, out_size);
}

// round 15
// speedup vs baseline: 1.0014x; 1.0014x over previous
#include <cuda_runtime.h>
#include <cuda_bf16.h>
#include <math.h>

// ---------------- device state (no allocations allowed) ----------------
__device__ float g_h2[2 * 1024];        // prefill hidden (2 tokens)
__device__ float g_hdec[1024];          // decode hidden
__device__ float g_q[2 * 1024];         // roped q per token
__device__ float g_kc[2][16][1024];     // k cache [layer][pos][NH*HD]
__device__ float g_vc[2][16][1024];     // v cache
__device__ float g_ff[2 * 4096];        // mlp intermediate
__device__ float g_logits[2048];
__device__ float g_embed_sum[1024];
__device__ int   g_codes[16];

// ---------------- helpers ----------------
__device__ __forceinline__ float block_sum(float v, float* red) {
    int lane = threadIdx.x & 31, w = threadIdx.x >> 5;
    #pragma unroll
    for (int o = 16; o; o >>= 1) v += __shfl_xor_sync(0xffffffffu, v, o);
    if (lane == 0) red[w] = v;
    __syncthreads();
    float r = (threadIdx.x < (blockDim.x >> 5)) ? red[threadIdx.x] : 0.f;
    if (w == 0) {
        #pragma unroll
        for (int o = 16; o; o >>= 1) r += __shfl_xor_sync(0xffffffffu, r, o);
        if (lane == 0) red[0] = r;
    }
    __syncthreads();
    float out = red[0];
    __syncthreads();
    return out;
}

// redundant per-block RMS norm into shared memory
__device__ __forceinline__ void load_rms(const float* h, const float* w,
                                         float* xs, int T, float* red) {
    for (int t = 0; t < T; t++) {
        float ss = 0.f;
        for (int i = threadIdx.x; i < 1024; i += 256) {
            float v = h[t * 1024 + i];
            ss += v * v;
        }
        float tot = block_sum(ss, red);
        float rn = rsqrtf(tot * (1.f / 1024.f) + 1e-6f);
        for (int i = threadIdx.x; i < 1024; i += 256)
            xs[t * 1024 + i] = h[t * 1024 + i] * rn * w[i];
    }
    __syncthreads();
}

__device__ __forceinline__ float gelu_tanh(float v) {
    float u = 0.7978845608028654f * (v + 0.044715f * v * v * v);
    return 0.5f * v * (1.f + tanhf(u));
}

// ---------------- kernels ----------------

__global__ void k_init(const float* __restrict__ talker,
                       const float* __restrict__ code0) {
    for (int i = threadIdx.x; i < 1024; i += 256) {
        g_h2[i]        = talker[i];
        g_h2[1024 + i] = code0[i];
        g_embed_sum[i] = code0[i];
    }
}

// QKV GEMV + RoPE + KV cache write. grid=96, block=256.
// pair index p in [0,1536): m = p>>9 (0=q,1=k,2=v), head=(p>>5)&15, d=p&31.
__global__ void k_qkv(const float* __restrict__ wq, const float* __restrict__ wk,
                      const float* __restrict__ wv, const float* __restrict__ ln1,
                      int l, int T, int p0, int hsel) {
    __shared__ float xs[2 * 1024];
    __shared__ float red[32];
    __shared__ float p1s[16][16][2];
    __shared__ float p2s[16][16][2];
    const float* h = hsel ? g_hdec : g_h2;
    load_rms(h, ln1 + l * 1024, xs, T, red);

    int pp = threadIdx.x & 15, ks = threadIdx.x >> 4;
    int pidx = blockIdx.x * 16 + pp;
    int m = pidx >> 9, head = (pidx >> 5) & 15, d = pidx & 31;
    const float* base = (m == 0) ? wq : ((m == 1) ? wk : wv);
    const float* W = base + (size_t)l * 1024 * 1024 + head * 64 + d;

    float a1[2] = {0.f, 0.f}, a2[2] = {0.f, 0.f};
    int i0 = ks * 64;
    #pragma unroll 4
    for (int i = i0; i < i0 + 64; i++) {
        float wa = W[(size_t)i * 1024];
        float wb = W[(size_t)i * 1024 + 32];
        a1[0] += xs[i] * wa; a2[0] += xs[i] * wb;
        if (T == 2) { a1[1] += xs[1024 + i] * wa; a2[1] += xs[1024 + i] * wb; }
    }
    p1s[ks][pp][0] = a1[0]; p2s[ks][pp][0] = a2[0];
    p1s[ks][pp][1] = a1[1]; p2s[ks][pp][1] = a2[1];
    __syncthreads();

    if (threadIdx.x < 16) {
        int ppi = threadIdx.x;
        int pidx2 = blockIdx.x * 16 + ppi;
        int mm = pidx2 >> 9, hh = (pidx2 >> 5) & 15, dd = pidx2 & 31;
        for (int t = 0; t < T; t++) {
            float s1 = 0.f, s2 = 0.f;
            #pragma unroll
            for (int k2 = 0; k2 < 16; k2++) { s1 += p1s[k2][ppi][t]; s2 += p2s[k2][ppi][t]; }
            float o1 = s1, o2 = s2;
            if (mm < 2) {
                float inv = powf(10000.f, -(float)dd * (1.f / 32.f));
                float ang = (float)(p0 + t) * inv;
                float c = cosf(ang), s = sinf(ang);
                o1 = s1 * c - s2 * s;
                o2 = s2 * c + s1 * s;
            }
            int off = hh * 64 + dd;
            if (mm == 0)      { g_q[t * 1024 + off] = o1; g_q[t * 1024 + off + 32] = o2; }
            else if (mm == 1) { g_kc[l][p0 + t][off] = o1; g_kc[l][p0 + t][off + 32] = o2; }
            else              { g_vc[l][p0 + t][off] = o1; g_vc[l][p0 + t][off + 32] = o2; }
        }
    }
}

// fused attention (redundant per block) + o-proj GEMV + residual. grid=64, block=256.
__global__ void k_attn_o(const float* __restrict__ wo, int l, int T, int p0, int hsel) {
    __shared__ float ao[2][1024];
    __shared__ float pr[16][16][2];
    float* h = hsel ? g_hdec : g_h2;
    int warp = threadIdx.x >> 5, lane = threadIdx.x & 31;

    for (int idx = warp; idx < T * 16; idx += 8) {
        int t = idx >> 4, hh = idx & 15;
        int S = p0 + t + 1;
        const float* qp = g_q + t * 1024 + hh * 64;
        float q0 = qp[lane], q1 = qp[lane + 32];
        float sc[16];
        for (int s = 0; s < S; s++) {
            const float* kp = &g_kc[l][s][hh * 64];
            float p = q0 * kp[lane] + q1 * kp[lane + 32];
            #pragma unroll
            for (int o = 16; o; o >>= 1) p += __shfl_xor_sync(0xffffffffu, p, o);
            sc[s] = p * 0.125f;
        }
        float mx = sc[0];
        for (int s = 1; s < S; s++) mx = fmaxf(mx, sc[s]);
        float den = 0.f;
        for (int s = 0; s < S; s++) { sc[s] = expf(sc[s] - mx); den += sc[s]; }
        float dn = 1.f / den;
        float o0 = 0.f, o1 = 0.f;
        for (int s = 0; s < S; s++) {
            const float* vp = &g_vc[l][s][hh * 64];
            float pw = sc[s] * dn;
            o0 += pw * vp[lane];
            o1 += pw * vp[lane + 32];
        }
        ao[t][hh * 64 + lane]      = o0;
        ao[t][hh * 64 + lane + 32] = o1;
    }
    __syncthreads();

    int c = threadIdx.x & 15, ks = threadIdx.x >> 4;
    int col = blockIdx.x * 16 + c;
    const float* W = wo + (size_t)l * 1024 * 1024 + col;
    float acc[2] = {0.f, 0.f};
    int i0 = ks * 64;
    #pragma unroll 4
    for (int i = i0; i < i0 + 64; i++) {
        float wv = W[(size_t)i * 1024];
        acc[0] += ao[0][i] * wv;
        if (T == 2) acc[1] += ao[1][i] * wv;
    }
    pr[ks][c][0] = acc[0]; pr[ks][c][1] = acc[1];
    __syncthreads();
    if (threadIdx.x < 16) {
        int cc = threadIdx.x;
        int col2 = blockIdx.x * 16 + cc;
        for (int t = 0; t < T; t++) {
            float s = 0.f;
            #pragma unroll
            for (int k2 = 0; k2 < 16; k2++) s += pr[k2][cc][t];
            h[t * 1024 + col2] += s;
        }
    }
}

// RMS + W1 GEMV + gelu -> g_ff. grid=128, block=256.
__global__ void k_mlp1(const float* __restrict__ w1, const float* __restrict__ ln2,
                       int l, int T, int hsel) {
    __shared__ float xs[2 * 1024];
    __shared__ float red[32];
    __shared__ float pr[8][32][2];
    const float* h = hsel ? g_hdec : g_h2;
    load_rms(h, ln2 + l * 1024, xs, T, red);

    int c = threadIdx.x & 31, ks = threadIdx.x >> 5;  // 8 slices x 128 rows
    int col = blockIdx.x * 32 + c;
    const float* W = w1 + (size_t)l * 1024 * 4096 + col;
    float acc[2] = {0.f, 0.f};
    int i0 = ks * 128;
    #pragma unroll 4
    for (int i = i0; i < i0 + 128; i++) {
        float wv = W[(size_t)i * 4096];
        acc[0] += xs[i] * wv;
        if (T == 2) acc[1] += xs[1024 + i] * wv;
    }
    pr[ks][c][0] = acc[0]; pr[ks][c][1] = acc[1];
    __syncthreads();
    if (threadIdx.x < 32) {
        int cc = threadIdx.x;
        int col2 = blockIdx.x * 32 + cc;
        for (int t = 0; t < T; t++) {
            float s = 0.f;
            #pragma unroll
            for (int k2 = 0; k2 < 8; k2++) s += pr[k2][cc][t];
            g_ff[t * 4096 + col2] = gelu_tanh(s);
        }
    }
}

// W2 GEMV + residual. grid=128, block=256.
__global__ void k_mlp2(const float* __restrict__ w2, int l, int T, int hsel) {
    __shared__ float ffs[2 * 4096];
    __shared__ float pr[32][8][2];
    float* h = hsel ? g_hdec : g_h2;
    for (int i = threadIdx.x; i < T * 4096; i += 256) ffs[i] = g_ff[i];
    __syncthreads();

    int c = threadIdx.x & 7, ks = threadIdx.x >> 3;  // 32 slices x 128 rows
    int col = blockIdx.x * 8 + c;
    const float* W = w2 + (size_t)l * 4096 * 1024 + col;
    float acc[2] = {0.f, 0.f};
    int i0 = ks * 128;
    #pragma unroll 4
    for (int i = i0; i < i0 + 128; i++) {
        float wv = W[(size_t)i * 1024];
        acc[0] += ffs[i] * wv;
        if (T == 2) acc[1] += ffs[4096 + i] * wv;
    }
    pr[ks][c][0] = acc[0]; pr[ks][c][1] = acc[1];
    __syncthreads();
    if (threadIdx.x < 8) {
        int cc = threadIdx.x;
        int col2 = blockIdx.x * 8 + cc;
        for (int t = 0; t < T; t++) {
            float s = 0.f;
            #pragma unroll
            for (int k2 = 0; k2 < 32; k2++) s += pr[k2][cc][t];
            h[t * 1024 + col2] += s;
        }
    }
}

// hidden = rms(h,ln_f); logits = heads[g] @ hidden. grid=128, block=256 (8 warps x 2 rows).
__global__ void k_logits(const float* __restrict__ heads, const float* __restrict__ lnf,
                         int g, int hsel) {
    __shared__ float hid[1024];
    __shared__ float red[32];
    const float* h = hsel ? g_hdec : (g_h2 + 1024);
    float ss = 0.f;
    for (int i = threadIdx.x; i < 1024; i += 256) { float v = h[i]; ss += v * v; }
    float tot = block_sum(ss, red);
    float rn = rsqrtf(tot * (1.f / 1024.f) + 1e-6f);
    for (int i = threadIdx.x; i < 1024; i += 256) hid[i] = h[i] * rn * lnf[i];
    __syncthreads();

    int warp = threadIdx.x >> 5, lane = threadIdx.x & 31;
    const float4* xp = (const float4*)hid;
    for (int r = 0; r < 2; r++) {
        int row = blockIdx.x * 16 + warp * 2 + r;
        const float4* rp = (const float4*)(heads + ((size_t)g * 2048 + row) * 1024);
        float acc = 0.f;
        #pragma unroll 8
        for (int j = lane; j < 256; j += 32) {
            float4 a = rp[j], b = xp[j];
            acc += a.x * b.x + a.y * b.y + a.z * b.z + a.w * b.w;
        }
        #pragma unroll
        for (int o = 16; o; o >>= 1) acc += __shfl_xor_sync(0xffffffffu, acc, o);
        if (lane == 0) g_logits[row] = acc;
    }
}

// top-50 (bitonic full sort) + softmax sampling + embed gather/accumulate. 1 block, 256 thr.
__global__ void k_sample(const float* __restrict__ embeds, const float* __restrict__ temp,
                         const float* __restrict__ uniforms, int g) {
    __shared__ unsigned long long keys[2048];
    __shared__ int s_code;
    int tid = threadIdx.x;
    for (int v = tid; v < 2048; v += 256) {
        unsigned int b = __float_as_uint(g_logits[v]);
        unsigned int ord = (b & 0x80000000u) ? ~b : (b | 0x80000000u);
        keys[v] = ((unsigned long long)ord << 32) | (unsigned int)(2047 - v);
    }
    __syncthreads();
    // descending bitonic sort (primary: value desc, secondary: index asc)
    for (int k = 2; k <= 2048; k <<= 1) {
        for (int j = k >> 1; j > 0; j >>= 1) {
            for (int i = tid; i < 2048; i += 256) {
                int ixj = i ^ j;
                if (ixj > i) {
                    bool dir = ((i & k) == 0);  // true => descending segment
                    unsigned long long a = keys[i], b2 = keys[ixj];
                    if (dir ? (a < b2) : (a > b2)) { keys[i] = b2; keys[ixj] = a; }
                }
            }
            __syncthreads();
        }
    }
    if (tid == 0) {
        float t = fmaxf(temp[0], 1e-5f);
        float topv[50];
        int topi[50];
        for (int i = 0; i < 50; i++) {
            unsigned long long kk = keys[i];
            unsigned int ord = (unsigned int)(kk >> 32);
            unsigned int b = (ord & 0x80000000u) ? (ord & 0x7fffffffu) : ~ord;
            topv[i] = __uint_as_float(b);
            topi[i] = 2047 - (int)(kk & 0xffffffffu);
        }
        float inv_t = 1.f / t;
        float mx = topv[0] * inv_t;
        float e[50];
        float den = 0.f;
        for (int i = 0; i < 50; i++) { e[i] = expf(topv[i] * inv_t - mx); den += e[i]; }
        float u = uniforms[g];
        u = fminf(fmaxf(u, 1e-6f), 1.f - 1e-6f);
        float cdf = 0.f;
        int choice = 0;
        bool found = false;
        for (int i = 0; i < 50; i++) {
            cdf += e[i] / den;
            if (!found && cdf >= u) { choice = i; found = true; }
        }
        s_code = topi[choice];
        g_codes[g] = s_code;
    }
    __syncthreads();
    int code = s_code;
    const float* emb = embeds + ((size_t)g * 2048 + code) * 1024;
    for (int i = tid; i < 1024; i += 256) {
        float e2 = emb[i];
        g_embed_sum[i] += e2;
        g_hdec[i] = e2;  // input for next transformer step
    }
}

__global__ void k_out(float* __restrict__ out, int out_size) {
    for (int i = threadIdx.x; i < out_size && i < 1039; i += 256) {
        if (i < 15) out[i] = (float)g_codes[i];
        else        out[i] = g_embed_sum[i - 15];
    }
}

// ---------------- launch ----------------
extern "C" void kernel_launch(void* const* d_in, const int* in_sizes, int n_in,
                              void* d_out, int out_size) {
    (void)in_sizes; (void)n_in;
    const float* talker   = (const float*)d_in[0];
    const float* code0    = (const float*)d_in[1];
    const float* temp     = (const float*)d_in[2];
    const float* uniforms = (const float*)d_in[3];
    const float* heads    = (const float*)d_in[4];
    const float* embeds   = (const float*)d_in[5];
    const float* ln1      = (const float*)d_in[6];
    const float* ln2      = (const float*)d_in[7];
    const float* lnf      = (const float*)d_in[8];
    const float* wq       = (const float*)d_in[9];
    const float* wk       = (const float*)d_in[10];
    const float* wv       = (const float*)d_in[11];
    const float* wo       = (const float*)d_in[12];
    const float* w1       = (const float*)d_in[13];
    const float* w2       = (const float*)d_in[14];

    k_init<<<1, 256>>>(talker, code0);

    // prefill: T=2, positions 0..1, h buffer = g_h2 (hsel=0)
    for (int l = 0; l < 2; l++) {
        k_qkv  <<<96, 256>>>(wq, wk, wv, ln1, l, 2, 0, 0);
        k_attn_o<<<64, 256>>>(wo, l, 2, 0, 0);
        k_mlp1 <<<128, 256>>>(w1, ln2, l, 2, 0);
        k_mlp2 <<<128, 256>>>(w2, l, 2, 0);
    }

    for (int g = 0; g < 15; g++) {
        k_logits<<<128, 256>>>(heads, lnf, g, (g == 0) ? 0 : 1);
        k_sample<<<1, 256>>>(embeds, temp, uniforms, g);
        if (g < 14) {
            int p0 = g + 2;  // new token position; cache len before step = p0
            for (int l = 0; l < 2; l++) {
                k_qkv  <<<96, 256>>>(wq, wk, wv, ln1, l, 1, p0, 1);
                k_attn_o<<<64, 256>>>(wo, l, 1, p0, 1);
                k_mlp1 <<<128, 256>>>(w1, ln2, l, 1, 1);
                k_mlp2 <<<128, 256>>>(w2, l, 1, 1);
            }
        }
    }

    k_out<<<1, 256>>>((float*)d_out, out_size);
}

// round 16
// speedup vs baseline: 1.6062x; 1.6040x over previous
#include <cuda_runtime.h>
#include <cuda_bf16.h>
#include <math.h>

// ---------------- device state (no allocations allowed) ----------------
__device__ float g_h2[2 * 1024];        // prefill hidden (2 tokens)
__device__ float g_hdec[1024];          // decode hidden
__device__ float g_q[2 * 1024];         // raw (un-roped) q per token
__device__ float g_kc[2][16][1024];     // raw k cache [layer][pos][NH*HD]
__device__ float g_vc[2][16][1024];     // v cache
__device__ float g_ff[2 * 4096];        // mlp intermediate
__device__ float g_logits[2048];
__device__ float g_embed_sum[1024];
__device__ int   g_codes[16];

// ---------------- helpers ----------------
__device__ __forceinline__ float block_sum(float v, float* red) {
    int lane = threadIdx.x & 31, w = threadIdx.x >> 5;
    #pragma unroll
    for (int o = 16; o; o >>= 1) v += __shfl_xor_sync(0xffffffffu, v, o);
    if (lane == 0) red[w] = v;
    __syncthreads();
    float r = (threadIdx.x < (blockDim.x >> 5)) ? red[threadIdx.x] : 0.f;
    if (w == 0) {
        #pragma unroll
        for (int o = 16; o; o >>= 1) r += __shfl_xor_sync(0xffffffffu, r, o);
        if (lane == 0) red[0] = r;
    }
    __syncthreads();
    float out = red[0];
    __syncthreads();
    return out;
}

// redundant per-block RMS norm into shared memory
__device__ __forceinline__ void load_rms(const float* h, const float* w,
                                         float* xs, int T, float* red) {
    for (int t = 0; t < T; t++) {
        float ss = 0.f;
        for (int i = threadIdx.x; i < 1024; i += 256) {
            float v = h[t * 1024 + i];
            ss += v * v;
        }
        float tot = block_sum(ss, red);
        float rn = rsqrtf(tot * (1.f / 1024.f) + 1e-6f);
        for (int i = threadIdx.x; i < 1024; i += 256)
            xs[t * 1024 + i] = h[t * 1024 + i] * rn * w[i];
    }
    __syncthreads();
}

__device__ __forceinline__ float gelu_tanh(float v) {
    float u = 0.7978845608028654f * (v + 0.044715f * v * v * v);
    return 0.5f * v * (1.f + tanhf(u));
}

__device__ __forceinline__ void f4acc(float4& a, float x, const float4& w) {
    a.x += x * w.x; a.y += x * w.y; a.z += x * w.z; a.w += x * w.w;
}
__device__ __forceinline__ void f4add(float4& a, const float4& b) {
    a.x += b.x; a.y += b.y; a.z += b.z; a.w += b.w;
}
__device__ __forceinline__ void f4shfl(float4& a, int o) {
    a.x += __shfl_xor_sync(0xffffffffu, a.x, o);
    a.y += __shfl_xor_sync(0xffffffffu, a.y, o);
    a.z += __shfl_xor_sync(0xffffffffu, a.z, o);
    a.w += __shfl_xor_sync(0xffffffffu, a.w, o);
}

// ---------------- kernels ----------------

__global__ void k_init(const float* __restrict__ talker,
                       const float* __restrict__ code0) {
    for (int i = threadIdx.x; i < 1024; i += 256) {
        g_h2[i]        = talker[i];
        g_h2[1024 + i] = code0[i];
        g_embed_sum[i] = code0[i];
    }
}

// QKV triple GEMV (raw outputs, RoPE applied later in attention).
// grid=192, block=256. 16-col tile per block; tiles 0-63:q, 64-127:k, 128-191:v.
__global__ void k_qkv(const float* __restrict__ wq, const float* __restrict__ wk,
                      const float* __restrict__ wv, const float* __restrict__ ln1,
                      int l, int T, int p0, int hsel) {
    __shared__ float xs[2 * 1024];
    __shared__ float red[32];
    __shared__ float4 part[2][8][4];
    const float* h = hsel ? g_hdec : g_h2;
    load_rms(h, ln1 + l * 1024, xs, T, red);

    int t = threadIdx.x;
    int c4 = t & 3, ks = t >> 2;          // 64 k-slices x 16 rows
    int warp = t >> 5, lane = t & 31;
    int m = blockIdx.x >> 6;
    int l0 = (blockIdx.x & 63) * 16;
    const float* base = (m == 0) ? wq : ((m == 1) ? wk : wv);
    const float* W = base + (size_t)l * 1024 * 1024 + l0 + c4 * 4;

    float4 a0 = make_float4(0.f, 0.f, 0.f, 0.f), a1 = a0;
    int r0 = ks * 16;
    #pragma unroll
    for (int r = 0; r < 16; r++) {
        float4 w4 = *(const float4*)(W + (size_t)(r0 + r) * 1024);
        f4acc(a0, xs[r0 + r], w4);
        if (T == 2) f4acc(a1, xs[1024 + r0 + r], w4);
    }
    #pragma unroll
    for (int o = 4; o <= 16; o <<= 1) { f4shfl(a0, o); if (T == 2) f4shfl(a1, o); }
    if (lane < 4) { part[0][warp][lane] = a0; part[1][warp][lane] = a1; }
    __syncthreads();
    if (t < 4) {
        for (int tok = 0; tok < T; tok++) {
            float4 s = part[tok][0][t];
            #pragma unroll
            for (int w = 1; w < 8; w++) f4add(s, part[tok][w][t]);
            int col = l0 + t * 4;
            float* dst = (m == 0) ? &g_q[tok * 1024 + col]
                       : (m == 1) ? &g_kc[l][p0 + tok][col]
                                  : &g_vc[l][p0 + tok][col];
            dst[0] = s.x; dst[1] = s.y; dst[2] = s.z; dst[3] = s.w;
        }
    }
}

// attention (RoPE at use, redundant per block) + o-proj GEMV + residual.
// grid=128, block=256; 8-col tile per block.
__global__ void k_attn_o(const float* __restrict__ wo, int l, int T, int p0, int hsel) {
    __shared__ float ao[2][1024];
    __shared__ float4 part[2][8][2];
    float* h = hsel ? g_hdec : g_h2;
    int warp = threadIdx.x >> 5, lane = threadIdx.x & 31;
    float inv = powf(10000.f, -(float)lane / 32.f);

    for (int idx = warp; idx < T * 16; idx += 8) {
        int t = idx >> 4, hh = idx & 15;
        int S = p0 + t + 1;
        const float* qp = g_q + t * 1024 + hh * 64;
        float q0 = qp[lane], q1 = qp[lane + 32];
        float qa = (float)(p0 + t) * inv;
        float qc = cosf(qa), qs = sinf(qa);
        float q0r = q0 * qc - q1 * qs;
        float q1r = q1 * qc + q0 * qs;
        float sc[16];
        for (int s = 0; s < S; s++) {
            const float* kp = &g_kc[l][s][hh * 64];
            float k0 = kp[lane], k1 = kp[lane + 32];
            float ka = (float)s * inv;
            float kc = cosf(ka), kss = sinf(ka);
            float k0r = k0 * kc - k1 * kss;
            float k1r = k1 * kc + k0 * kss;
            float p = q0r * k0r + q1r * k1r;
            #pragma unroll
            for (int o = 16; o; o >>= 1) p += __shfl_xor_sync(0xffffffffu, p, o);
            sc[s] = p * 0.125f;
        }
        float mx = sc[0];
        for (int s = 1; s < S; s++) mx = fmaxf(mx, sc[s]);
        float den = 0.f;
        for (int s = 0; s < S; s++) { sc[s] = expf(sc[s] - mx); den += sc[s]; }
        float dn = 1.f / den;
        float o0 = 0.f, o1 = 0.f;
        for (int s = 0; s < S; s++) {
            const float* vp = &g_vc[l][s][hh * 64];
            float pw = sc[s] * dn;
            o0 += pw * vp[lane];
            o1 += pw * vp[lane + 32];
        }
        ao[t][hh * 64 + lane]      = o0;
        ao[t][hh * 64 + lane + 32] = o1;
    }
    __syncthreads();

    int c4 = threadIdx.x & 1, ks = threadIdx.x >> 1;   // 128 k-slices x 8 rows
    int col0 = blockIdx.x * 8;
    const float* W = wo + (size_t)l * 1024 * 1024 + col0 + c4 * 4;
    float4 a0 = make_float4(0.f, 0.f, 0.f, 0.f), a1 = a0;
    int r0 = ks * 8;
    #pragma unroll
    for (int r = 0; r < 8; r++) {
        float4 w4 = *(const float4*)(W + (size_t)(r0 + r) * 1024);
        f4acc(a0, ao[0][r0 + r], w4);
        if (T == 2) f4acc(a1, ao[1][r0 + r], w4);
    }
    #pragma unroll
    for (int o = 2; o <= 16; o <<= 1) { f4shfl(a0, o); if (T == 2) f4shfl(a1, o); }
    if (lane < 2) { part[0][warp][lane] = a0; part[1][warp][lane] = a1; }
    __syncthreads();
    if (threadIdx.x < 2) {
        for (int tok = 0; tok < T; tok++) {
            float4 s = part[tok][0][threadIdx.x];
            #pragma unroll
            for (int w = 1; w < 8; w++) f4add(s, part[tok][w][threadIdx.x]);
            float* dst = &h[tok * 1024 + col0 + threadIdx.x * 4];
            dst[0] += s.x; dst[1] += s.y; dst[2] += s.z; dst[3] += s.w;
        }
    }
}

// RMS + W1 GEMV + gelu -> g_ff. grid=256, block=256; 16-col tile.
__global__ void k_mlp1(const float* __restrict__ w1, const float* __restrict__ ln2,
                       int l, int T, int hsel) {
    __shared__ float xs[2 * 1024];
    __shared__ float red[32];
    __shared__ float4 part[2][8][4];
    const float* h = hsel ? g_hdec : g_h2;
    load_rms(h, ln2 + l * 1024, xs, T, red);

    int t = threadIdx.x;
    int c4 = t & 3, ks = t >> 2;          // 64 k-slices x 16 rows
    int warp = t >> 5, lane = t & 31;
    int col0 = blockIdx.x * 16;
    const float* W = w1 + (size_t)l * 1024 * 4096 + col0 + c4 * 4;

    float4 a0 = make_float4(0.f, 0.f, 0.f, 0.f), a1 = a0;
    int r0 = ks * 16;
    #pragma unroll
    for (int r = 0; r < 16; r++) {
        float4 w4 = *(const float4*)(W + (size_t)(r0 + r) * 4096);
        f4acc(a0, xs[r0 + r], w4);
        if (T == 2) f4acc(a1, xs[1024 + r0 + r], w4);
    }
    #pragma unroll
    for (int o = 4; o <= 16; o <<= 1) { f4shfl(a0, o); if (T == 2) f4shfl(a1, o); }
    if (lane < 4) { part[0][warp][lane] = a0; part[1][warp][lane] = a1; }
    __syncthreads();
    if (t < 4) {
        for (int tok = 0; tok < T; tok++) {
            float4 s = part[tok][0][t];
            #pragma unroll
            for (int w = 1; w < 8; w++) f4add(s, part[tok][w][t]);
            float* dst = &g_ff[tok * 4096 + col0 + t * 4];
            dst[0] = gelu_tanh(s.x); dst[1] = gelu_tanh(s.y);
            dst[2] = gelu_tanh(s.z); dst[3] = gelu_tanh(s.w);
        }
    }
}

// W2 GEMV + residual. grid=128, block=256; 8-col tile, K=4096.
__global__ void k_mlp2(const float* __restrict__ w2, int l, int T, int hsel) {
    __shared__ float ffs[2 * 4096];
    __shared__ float4 part[2][8][2];
    float* h = hsel ? g_hdec : g_h2;
    for (int i = threadIdx.x; i < T * 4096; i += 256) ffs[i] = g_ff[i];
    __syncthreads();

    int c4 = threadIdx.x & 1, ks = threadIdx.x >> 1;   // 128 k-slices x 32 rows
    int warp = threadIdx.x >> 5, lane = threadIdx.x & 31;
    int col0 = blockIdx.x * 8;
    const float* W = w2 + (size_t)l * 4096 * 1024 + col0 + c4 * 4;
    float4 a0 = make_float4(0.f, 0.f, 0.f, 0.f), a1 = a0;
    int r0 = ks * 32;
    #pragma unroll
    for (int r = 0; r < 32; r++) {
        float4 w4 = *(const float4*)(W + (size_t)(r0 + r) * 1024);
        f4acc(a0, ffs[r0 + r], w4);
        if (T == 2) f4acc(a1, ffs[4096 + r0 + r], w4);
    }
    #pragma unroll
    for (int o = 2; o <= 16; o <<= 1) { f4shfl(a0, o); if (T == 2) f4shfl(a1, o); }
    if (lane < 2) { part[0][warp][lane] = a0; part[1][warp][lane] = a1; }
    __syncthreads();
    if (threadIdx.x < 2) {
        for (int tok = 0; tok < T; tok++) {
            float4 s = part[tok][0][threadIdx.x];
            #pragma unroll
            for (int w = 1; w < 8; w++) f4add(s, part[tok][w][threadIdx.x]);
            float* dst = &h[tok * 1024 + col0 + threadIdx.x * 4];
            dst[0] += s.x; dst[1] += s.y; dst[2] += s.z; dst[3] += s.w;
        }
    }
}

// hidden = rms(h,ln_f); logits = heads[g] @ hidden. grid=128, block=256.
// heads loaded with streaming hint (read-once, protect L2 weight residency).
__global__ void k_logits(const float* __restrict__ heads, const float* __restrict__ lnf,
                         int g, int hsel) {
    __shared__ float hid[1024];
    __shared__ float red[32];
    const float* h = hsel ? g_hdec : (g_h2 + 1024);
    float ss = 0.f;
    for (int i = threadIdx.x; i < 1024; i += 256) { float v = h[i]; ss += v * v; }
    float tot = block_sum(ss, red);
    float rn = rsqrtf(tot * (1.f / 1024.f) + 1e-6f);
    for (int i = threadIdx.x; i < 1024; i += 256) hid[i] = h[i] * rn * lnf[i];
    __syncthreads();

    int warp = threadIdx.x >> 5, lane = threadIdx.x & 31;
    const float4* xp = (const float4*)hid;
    for (int r = 0; r < 2; r++) {
        int row = blockIdx.x * 16 + warp * 2 + r;
        const float4* rp = (const float4*)(heads + ((size_t)g * 2048 + row) * 1024);
        float acc = 0.f;
        #pragma unroll 8
        for (int j = lane; j < 256; j += 32) {
            float4 a = __ldcs(rp + j);
            float4 b = xp[j];
            acc += a.x * b.x + a.y * b.y + a.z * b.z + a.w * b.w;
        }
        #pragma unroll
        for (int o = 16; o; o >>= 1) acc += __shfl_xor_sync(0xffffffffu, acc, o);
        if (lane == 0) g_logits[row] = acc;
    }
}

// top-50 (bitonic full sort) + softmax sampling + embed gather/accumulate. 1 block, 256 thr.
__global__ void k_sample(const float* __restrict__ embeds, const float* __restrict__ temp,
                         const float* __restrict__ uniforms, int g) {
    __shared__ unsigned long long keys[2048];
    __shared__ int s_code;
    int tid = threadIdx.x;
    for (int v = tid; v < 2048; v += 256) {
        unsigned int b = __float_as_uint(g_logits[v]);
        unsigned int ord = (b & 0x80000000u) ? ~b : (b | 0x80000000u);
        keys[v] = ((unsigned long long)ord << 32) | (unsigned int)(2047 - v);
    }
    __syncthreads();
    for (int k = 2; k <= 2048; k <<= 1) {
        for (int j = k >> 1; j > 0; j >>= 1) {
            for (int i = tid; i < 2048; i += 256) {
                int ixj = i ^ j;
                if (ixj > i) {
                    bool dir = ((i & k) == 0);
                    unsigned long long a = keys[i], b2 = keys[ixj];
                    if (dir ? (a < b2) : (a > b2)) { keys[i] = b2; keys[ixj] = a; }
                }
            }
            __syncthreads();
        }
    }
    if (tid == 0) {
        float t = fmaxf(temp[0], 1e-5f);
        float topv[50];
        int topi[50];
        for (int i = 0; i < 50; i++) {
            unsigned long long kk = keys[i];
            unsigned int ord = (unsigned int)(kk >> 32);
            unsigned int b = (ord & 0x80000000u) ? (ord & 0x7fffffffu) : ~ord;
            topv[i] = __uint_as_float(b);
            topi[i] = 2047 - (int)(kk & 0xffffffffu);
        }
        float inv_t = 1.f / t;
        float mx = topv[0] * inv_t;
        float e[50];
        float den = 0.f;
        for (int i = 0; i < 50; i++) { e[i] = expf(topv[i] * inv_t - mx); den += e[i]; }
        float u = uniforms[g];
        u = fminf(fmaxf(u, 1e-6f), 1.f - 1e-6f);
        float cdf = 0.f;
        int choice = 0;
        bool found = false;
        for (int i = 0; i < 50; i++) {
            cdf += e[i] / den;
            if (!found && cdf >= u) { choice = i; found = true; }
        }
        s_code = topi[choice];
        g_codes[g] = s_code;
    }
    __syncthreads();
    int code = s_code;
    const float* emb = embeds + ((size_t)g * 2048 + code) * 1024;
    for (int i = tid; i < 1024; i += 256) {
        float e2 = emb[i];
        g_embed_sum[i] += e2;
        g_hdec[i] = e2;
    }
}

__global__ void k_out(float* __restrict__ out, int out_size) {
    for (int i = threadIdx.x; i < out_size && i < 1039; i += 256) {
        if (i < 15) out[i] = (float)g_codes[i];
        else        out[i] = g_embed_sum[i - 15];
    }
}

// ---------------- launch ----------------
extern "C" void kernel_launch(void* const* d_in, const int* in_sizes, int n_in,
                              void* d_out, int out_size) {
    (void)in_sizes; (void)n_in;
    const float* talker   = (const float*)d_in[0];
    const float* code0    = (const float*)d_in[1];
    const float* temp     = (const float*)d_in[2];
    const float* uniforms = (const float*)d_in[3];
    const float* heads    = (const float*)d_in[4];
    const float* embeds   = (const float*)d_in[5];
    const float* ln1      = (const float*)d_in[6];
    const float* ln2      = (const float*)d_in[7];
    const float* lnf      = (const float*)d_in[8];
    const float* wq       = (const float*)d_in[9];
    const float* wk       = (const float*)d_in[10];
    const float* wv       = (const float*)d_in[11];
    const float* wo       = (const float*)d_in[12];
    const float* w1       = (const float*)d_in[13];
    const float* w2       = (const float*)d_in[14];

    k_init<<<1, 256>>>(talker, code0);

    // prefill: T=2, positions 0..1
    for (int l = 0; l < 2; l++) {
        k_qkv   <<<192, 256>>>(wq, wk, wv, ln1, l, 2, 0, 0);
        k_attn_o<<<128, 256>>>(wo, l, 2, 0, 0);
        k_mlp1  <<<256, 256>>>(w1, ln2, l, 2, 0);
        k_mlp2  <<<128, 256>>>(w2, l, 2, 0);
    }

    for (int g = 0; g < 15; g++) {
        k_logits<<<128, 256>>>(heads, lnf, g, (g == 0) ? 0 : 1);
        k_sample<<<1, 256>>>(embeds, temp, uniforms, g);
        if (g < 14) {
            int p0 = g + 2;
            for (int l = 0; l < 2; l++) {
                k_qkv   <<<192, 256>>>(wq, wk, wv, ln1, l, 1, p0, 1);
                k_attn_o<<<128, 256>>>(wo, l, 1, p0, 1);
                k_mlp1  <<<256, 256>>>(w1, ln2, l, 1, 1);
                k_mlp2  <<<128, 256>>>(w2, l, 1, 1);
            }
        }
    }

    k_out<<<1, 256>>>((float*)d_out, out_size);
}

// round 17
// speedup vs baseline: 1.6382x; 1.0199x over previous
#include <cuda_runtime.h>
#include <cuda_bf16.h>
#include <math.h>

// ---------------- device state (no allocations allowed) ----------------
__device__ float g_h2[2 * 1024];        // prefill hidden (2 tokens)
__device__ float g_hdec[1024];          // decode hidden
__device__ float g_q[2 * 1024];         // raw (un-roped) q per token
__device__ float g_kc[2][16][1024];     // raw k cache [layer][pos][NH*HD]
__device__ float g_vc[2][16][1024];     // v cache
__device__ float g_ff[2 * 4096];        // mlp intermediate
__device__ float g_logits[2048];
__device__ float g_embed_sum[1024];
__device__ int   g_codes[16];

// ---------------- helpers ----------------
__device__ __forceinline__ float block_sum(float v, float* red) {
    int lane = threadIdx.x & 31, w = threadIdx.x >> 5;
    #pragma unroll
    for (int o = 16; o; o >>= 1) v += __shfl_xor_sync(0xffffffffu, v, o);
    if (lane == 0) red[w] = v;
    __syncthreads();
    float r = (threadIdx.x < (blockDim.x >> 5)) ? red[threadIdx.x] : 0.f;
    if (w == 0) {
        #pragma unroll
        for (int o = 16; o; o >>= 1) r += __shfl_xor_sync(0xffffffffu, r, o);
        if (lane == 0) red[0] = r;
    }
    __syncthreads();
    float out = red[0];
    __syncthreads();
    return out;
}

// redundant per-block RMS norm into shared memory
__device__ __forceinline__ void load_rms(const float* h, const float* w,
                                         float* xs, int T, float* red) {
    for (int t = 0; t < T; t++) {
        float ss = 0.f;
        for (int i = threadIdx.x; i < 1024; i += 256) {
            float v = h[t * 1024 + i];
            ss += v * v;
        }
        float tot = block_sum(ss, red);
        float rn = rsqrtf(tot * (1.f / 1024.f) + 1e-6f);
        for (int i = threadIdx.x; i < 1024; i += 256)
            xs[t * 1024 + i] = h[t * 1024 + i] * rn * w[i];
    }
    __syncthreads();
}

__device__ __forceinline__ float gelu_tanh(float v) {
    float u = 0.7978845608028654f * (v + 0.044715f * v * v * v);
    return 0.5f * v * (1.f + tanhf(u));
}

__device__ __forceinline__ void f4acc(float4& a, float x, const float4& w) {
    a.x += x * w.x; a.y += x * w.y; a.z += x * w.z; a.w += x * w.w;
}
__device__ __forceinline__ void f4add(float4& a, const float4& b) {
    a.x += b.x; a.y += b.y; a.z += b.z; a.w += b.w;
}
__device__ __forceinline__ void f4shfl(float4& a, int o) {
    a.x += __shfl_xor_sync(0xffffffffu, a.x, o);
    a.y += __shfl_xor_sync(0xffffffffu, a.y, o);
    a.z += __shfl_xor_sync(0xffffffffu, a.z, o);
    a.w += __shfl_xor_sync(0xffffffffu, a.w, o);
}

// ---------------- kernels ----------------

__global__ void k_init(const float* __restrict__ talker,
                       const float* __restrict__ code0) {
    for (int i = threadIdx.x; i < 1024; i += 256) {
        g_h2[i]        = talker[i];
        g_h2[1024 + i] = code0[i];
        g_embed_sum[i] = code0[i];
    }
}

// QKV triple GEMV (raw outputs, RoPE applied later in attention).
// grid=192, block=256. 16-col tile per block; tiles 0-63:q, 64-127:k, 128-191:v.
__global__ void k_qkv(const float* __restrict__ wq, const float* __restrict__ wk,
                      const float* __restrict__ wv, const float* __restrict__ ln1,
                      int l, int T, int p0, int hsel) {
    __shared__ float xs[2 * 1024];
    __shared__ float red[32];
    __shared__ float4 part[2][8][4];
    const float* h = hsel ? g_hdec : g_h2;
    load_rms(h, ln1 + l * 1024, xs, T, red);

    int t = threadIdx.x;
    int c4 = t & 3, ks = t >> 2;          // 64 k-slices x 16 rows
    int warp = t >> 5, lane = t & 31;
    int m = blockIdx.x >> 6;
    int l0 = (blockIdx.x & 63) * 16;
    const float* base = (m == 0) ? wq : ((m == 1) ? wk : wv);
    const float* W = base + (size_t)l * 1024 * 1024 + l0 + c4 * 4;

    float4 a0 = make_float4(0.f, 0.f, 0.f, 0.f), a1 = a0;
    int r0 = ks * 16;
    #pragma unroll
    for (int r = 0; r < 16; r++) {
        float4 w4 = *(const float4*)(W + (size_t)(r0 + r) * 1024);
        f4acc(a0, xs[r0 + r], w4);
        if (T == 2) f4acc(a1, xs[1024 + r0 + r], w4);
    }
    #pragma unroll
    for (int o = 4; o <= 16; o <<= 1) { f4shfl(a0, o); if (T == 2) f4shfl(a1, o); }
    if (lane < 4) { part[0][warp][lane] = a0; part[1][warp][lane] = a1; }
    __syncthreads();
    if (t < 4) {
        for (int tok = 0; tok < T; tok++) {
            float4 s = part[tok][0][t];
            #pragma unroll
            for (int w = 1; w < 8; w++) f4add(s, part[tok][w][t]);
            int col = l0 + t * 4;
            float* dst = (m == 0) ? &g_q[tok * 1024 + col]
                       : (m == 1) ? &g_kc[l][p0 + tok][col]
                                  : &g_vc[l][p0 + tok][col];
            dst[0] = s.x; dst[1] = s.y; dst[2] = s.z; dst[3] = s.w;
        }
    }
}

// attention (RoPE at use, redundant per block) + o-proj GEMV + residual.
// grid=128, block=256; 8-col tile per block.
__global__ void k_attn_o(const float* __restrict__ wo, int l, int T, int p0, int hsel) {
    __shared__ float ao[2][1024];
    __shared__ float4 part[2][8][2];
    float* h = hsel ? g_hdec : g_h2;
    int warp = threadIdx.x >> 5, lane = threadIdx.x & 31;
    float inv = powf(10000.f, -(float)lane / 32.f);

    for (int idx = warp; idx < T * 16; idx += 8) {
        int t = idx >> 4, hh = idx & 15;
        int S = p0 + t + 1;
        const float* qp = g_q + t * 1024 + hh * 64;
        float q0 = qp[lane], q1 = qp[lane + 32];
        float qa = (float)(p0 + t) * inv;
        float qc = cosf(qa), qs = sinf(qa);
        float q0r = q0 * qc - q1 * qs;
        float q1r = q1 * qc + q0 * qs;
        float sc[16];
        for (int s = 0; s < S; s++) {
            const float* kp = &g_kc[l][s][hh * 64];
            float k0 = kp[lane], k1 = kp[lane + 32];
            float ka = (float)s * inv;
            float kc = cosf(ka), kss = sinf(ka);
            float k0r = k0 * kc - k1 * kss;
            float k1r = k1 * kc + k0 * kss;
            float p = q0r * k0r + q1r * k1r;
            #pragma unroll
            for (int o = 16; o; o >>= 1) p += __shfl_xor_sync(0xffffffffu, p, o);
            sc[s] = p * 0.125f;
        }
        float mx = sc[0];
        for (int s = 1; s < S; s++) mx = fmaxf(mx, sc[s]);
        float den = 0.f;
        for (int s = 0; s < S; s++) { sc[s] = expf(sc[s] - mx); den += sc[s]; }
        float dn = 1.f / den;
        float o0 = 0.f, o1 = 0.f;
        for (int s = 0; s < S; s++) {
            const float* vp = &g_vc[l][s][hh * 64];
            float pw = sc[s] * dn;
            o0 += pw * vp[lane];
            o1 += pw * vp[lane + 32];
        }
        ao[t][hh * 64 + lane]      = o0;
        ao[t][hh * 64 + lane + 32] = o1;
    }
    __syncthreads();

    int c4 = threadIdx.x & 1, ks = threadIdx.x >> 1;   // 128 k-slices x 8 rows
    int col0 = blockIdx.x * 8;
    const float* W = wo + (size_t)l * 1024 * 1024 + col0 + c4 * 4;
    float4 a0 = make_float4(0.f, 0.f, 0.f, 0.f), a1 = a0;
    int r0 = ks * 8;
    #pragma unroll
    for (int r = 0; r < 8; r++) {
        float4 w4 = *(const float4*)(W + (size_t)(r0 + r) * 1024);
        f4acc(a0, ao[0][r0 + r], w4);
        if (T == 2) f4acc(a1, ao[1][r0 + r], w4);
    }
    #pragma unroll
    for (int o = 2; o <= 16; o <<= 1) { f4shfl(a0, o); if (T == 2) f4shfl(a1, o); }
    if (lane < 2) { part[0][warp][lane] = a0; part[1][warp][lane] = a1; }
    __syncthreads();
    if (threadIdx.x < 2) {
        for (int tok = 0; tok < T; tok++) {
            float4 s = part[tok][0][threadIdx.x];
            #pragma unroll
            for (int w = 1; w < 8; w++) f4add(s, part[tok][w][threadIdx.x]);
            float* dst = &h[tok * 1024 + col0 + threadIdx.x * 4];
            dst[0] += s.x; dst[1] += s.y; dst[2] += s.z; dst[3] += s.w;
        }
    }
}

// RMS + W1 GEMV + gelu -> g_ff. grid=256, block=256; 16-col tile.
__global__ void k_mlp1(const float* __restrict__ w1, const float* __restrict__ ln2,
                       int l, int T, int hsel) {
    __shared__ float xs[2 * 1024];
    __shared__ float red[32];
    __shared__ float4 part[2][8][4];
    const float* h = hsel ? g_hdec : g_h2;
    load_rms(h, ln2 + l * 1024, xs, T, red);

    int t = threadIdx.x;
    int c4 = t & 3, ks = t >> 2;          // 64 k-slices x 16 rows
    int warp = t >> 5, lane = t & 31;
    int col0 = blockIdx.x * 16;
    const float* W = w1 + (size_t)l * 1024 * 4096 + col0 + c4 * 4;

    float4 a0 = make_float4(0.f, 0.f, 0.f, 0.f), a1 = a0;
    int r0 = ks * 16;
    #pragma unroll
    for (int r = 0; r < 16; r++) {
        float4 w4 = *(const float4*)(W + (size_t)(r0 + r) * 4096);
        f4acc(a0, xs[r0 + r], w4);
        if (T == 2) f4acc(a1, xs[1024 + r0 + r], w4);
    }
    #pragma unroll
    for (int o = 4; o <= 16; o <<= 1) { f4shfl(a0, o); if (T == 2) f4shfl(a1, o); }
    if (lane < 4) { part[0][warp][lane] = a0; part[1][warp][lane] = a1; }
    __syncthreads();
    if (t < 4) {
        for (int tok = 0; tok < T; tok++) {
            float4 s = part[tok][0][t];
            #pragma unroll
            for (int w = 1; w < 8; w++) f4add(s, part[tok][w][t]);
            float* dst = &g_ff[tok * 4096 + col0 + t * 4];
            dst[0] = gelu_tanh(s.x); dst[1] = gelu_tanh(s.y);
            dst[2] = gelu_tanh(s.z); dst[3] = gelu_tanh(s.w);
        }
    }
}

// W2 GEMV + residual. grid=128, block=256; 8-col tile, K=4096.
__global__ void k_mlp2(const float* __restrict__ w2, int l, int T, int hsel) {
    __shared__ float ffs[2 * 4096];
    __shared__ float4 part[2][8][2];
    float* h = hsel ? g_hdec : g_h2;
    for (int i = threadIdx.x; i < T * 4096; i += 256) ffs[i] = g_ff[i];
    __syncthreads();

    int c4 = threadIdx.x & 1, ks = threadIdx.x >> 1;   // 128 k-slices x 32 rows
    int warp = threadIdx.x >> 5, lane = threadIdx.x & 31;
    int col0 = blockIdx.x * 8;
    const float* W = w2 + (size_t)l * 4096 * 1024 + col0 + c4 * 4;
    float4 a0 = make_float4(0.f, 0.f, 0.f, 0.f), a1 = a0;
    int r0 = ks * 32;
    #pragma unroll
    for (int r = 0; r < 32; r++) {
        float4 w4 = *(const float4*)(W + (size_t)(r0 + r) * 1024);
        f4acc(a0, ffs[r0 + r], w4);
        if (T == 2) f4acc(a1, ffs[4096 + r0 + r], w4);
    }
    #pragma unroll
    for (int o = 2; o <= 16; o <<= 1) { f4shfl(a0, o); if (T == 2) f4shfl(a1, o); }
    if (lane < 2) { part[0][warp][lane] = a0; part[1][warp][lane] = a1; }
    __syncthreads();
    if (threadIdx.x < 2) {
        for (int tok = 0; tok < T; tok++) {
            float4 s = part[tok][0][threadIdx.x];
            #pragma unroll
            for (int w = 1; w < 8; w++) f4add(s, part[tok][w][threadIdx.x]);
            float* dst = &h[tok * 1024 + col0 + threadIdx.x * 4];
            dst[0] += s.x; dst[1] += s.y; dst[2] += s.z; dst[3] += s.w;
        }
    }
}

// hidden = rms(h,ln_f); logits = heads[g] @ hidden. grid=128, block=256.
// heads loaded with streaming hint (read-once, protect L2 weight residency).
__global__ void k_logits(const float* __restrict__ heads, const float* __restrict__ lnf,
                         int g, int hsel) {
    __shared__ float hid[1024];
    __shared__ float red[32];
    const float* h = hsel ? g_hdec : (g_h2 + 1024);
    float ss = 0.f;
    for (int i = threadIdx.x; i < 1024; i += 256) { float v = h[i]; ss += v * v; }
    float tot = block_sum(ss, red);
    float rn = rsqrtf(tot * (1.f / 1024.f) + 1e-6f);
    for (int i = threadIdx.x; i < 1024; i += 256) hid[i] = h[i] * rn * lnf[i];
    __syncthreads();

    int warp = threadIdx.x >> 5, lane = threadIdx.x & 31;
    const float4* xp = (const float4*)hid;
    for (int r = 0; r < 2; r++) {
        int row = blockIdx.x * 16 + warp * 2 + r;
        const float4* rp = (const float4*)(heads + ((size_t)g * 2048 + row) * 1024);
        float acc = 0.f;
        #pragma unroll 8
        for (int j = lane; j < 256; j += 32) {
            float4 a = __ldcs(rp + j);
            float4 b = xp[j];
            acc += a.x * b.x + a.y * b.y + a.z * b.z + a.w * b.w;
        }
        #pragma unroll
        for (int o = 16; o; o >>= 1) acc += __shfl_xor_sync(0xffffffffu, acc, o);
        if (lane == 0) g_logits[row] = acc;
    }
}

// top-50 (bitonic full sort) + softmax sampling + embed gather/accumulate. 1 block, 256 thr.
__global__ void k_sample(const float* __restrict__ embeds, const float* __restrict__ temp,
                         const float* __restrict__ uniforms, int g) {
    __shared__ unsigned long long keys[2048];
    __shared__ int s_code;
    int tid = threadIdx.x;
    for (int v = tid; v < 2048; v += 256) {
        unsigned int b = __float_as_uint(g_logits[v]);
        unsigned int ord = (b & 0x80000000u) ? ~b : (b | 0x80000000u);
        keys[v] = ((unsigned long long)ord << 32) | (unsigned int)(2047 - v);
    }
    __syncthreads();
    for (int k = 2; k <= 2048; k <<= 1) {
        for (int j = k >> 1; j > 0; j >>= 1) {
            for (int i = tid; i < 2048; i += 256) {
                int ixj = i ^ j;
                if (ixj > i) {
                    bool dir = ((i & k) == 0);
                    unsigned long long a = keys[i], b2 = keys[ixj];
                    if (dir ? (a < b2) : (a > b2)) { keys[i] = b2; keys[ixj] = a; }
                }
            }
            __syncthreads();
        }
    }
    if (tid == 0) {
        float t = fmaxf(temp[0], 1e-5f);
        float topv[50];
        int topi[50];
        for (int i = 0; i < 50; i++) {
            unsigned long long kk = keys[i];
            unsigned int ord = (unsigned int)(kk >> 32);
            unsigned int b = (ord & 0x80000000u) ? (ord & 0x7fffffffu) : ~ord;
            topv[i] = __uint_as_float(b);
            topi[i] = 2047 - (int)(kk & 0xffffffffu);
        }
        float inv_t = 1.f / t;
        float mx = topv[0] * inv_t;
        float e[50];
        float den = 0.f;
        for (int i = 0; i < 50; i++) { e[i] = expf(topv[i] * inv_t - mx); den += e[i]; }
        float u = uniforms[g];
        u = fminf(fmaxf(u, 1e-6f), 1.f - 1e-6f);
        float cdf = 0.f;
        int choice = 0;
        bool found = false;
        for (int i = 0; i < 50; i++) {
            cdf += e[i] / den;
            if (!found && cdf >= u) { choice = i; found = true; }
        }
        s_code = topi[choice];
        g_codes[g] = s_code;
    }
    __syncthreads();
    int code = s_code;
    const float* emb = embeds + ((size_t)g * 2048 + code) * 1024;
    for (int i = tid; i < 1024; i += 256) {
        float e2 = emb[i];
        g_embed_sum[i] += e2;
        g_hdec[i] = e2;
    }
}

__global__ void k_out(float* __restrict__ out, int out_size) {
    for (int i = threadIdx.x; i < out_size && i < 1039; i += 256) {
        if (i < 15) out[i] = (float)g_codes[i];
        else        out[i] = g_embed_sum[i - 15];
    }
}

// ---------------- launch ----------------
extern "C" void kernel_launch(void* const* d_in, const int* in_sizes, int n_in,
                              void* d_out, int out_size) {
    (void)in_sizes; (void)n_in;
    const float* talker   = (const float*)d_in[0];
    const float* code0    = (const float*)d_in[1];
    const float* temp     = (const float*)d_in[2];
    const float* uniforms = (const float*)d_in[3];
    const float* heads    = (const float*)d_in[4];
    const float* embeds   = (const float*)d_in[5];
    const float* ln1      = (const float*)d_in[6];
    const float* ln2      = (const float*)d_in[7];
    const float* lnf      = (const float*)d_in[8];
    const float* wq       = (const float*)d_in[9];
    const float* wk       = (const float*)d_in[10];
    const float* wv       = (const float*)d_in[11];
    const float* wo       = (const float*)d_in[12];
    const float* w1       = (const float*)d_in[13];
    const float* w2       = (const float*)d_in[14];

    k_init<<<1, 256>>>(talker, code0);

    // prefill: T=2, positions 0..1
    for (int l = 0; l < 2; l++) {
        k_qkv   <<<192, 256>>>(wq, wk, wv, ln1, l, 2, 0, 0);
        k_attn_o<<<128, 256>>>(wo, l, 2, 0, 0);
        k_mlp1  <<<256, 256>>>(w1, ln2, l, 2, 0);
        k_mlp2  <<<128, 256>>>(w2, l, 2, 0);
    }

    for (int g = 0; g < 15; g++) {
        k_logits<<<128, 256>>>(heads, lnf, g, (g == 0) ? 0 : 1);
        k_sample<<<1, 256>>>(embeds, temp, uniforms, g);
        if (g < 14) {
            int p0 = g + 2;
            for (int l = 0; l < 2; l++) {
                k_qkv   <<<192, 256>>>(wq, wk, wv, ln1, l, 1, p0, 1);
                k_attn_o<<<128, 256>>>(wo, l, 1, p0, 1);
                k_mlp1  <<<256, 256>>>(w1, ln2, l, 1, 1);
                k_mlp2  <<<128, 256>>>(w2, l, 1, 1);
            }
        }
    }

    k_out<<<1, 256>>>((float*)d_out, out_size);
}